// round 15
// baseline (speedup 1.0000x reference)
#include <cuda_runtime.h>
#include <cuda_fp16.h>
#include <cstdint>

#define Bn   4
#define CIN  64
#define Hc   128
#define Wc   128
#define COUT 64
#define DGn  8
#define KKn  9
#define HOn  128
#define WOn  128
#define CGn  8
#define HWp  (HOn * WOn)

// ---------------- scratch (device globals; no runtime alloc) ----------------
// x re-laid out per dg with Y-INTERLEAVE: [b][dg][y/2][x][y&1][cg] fp16.
// One 128B line = 2 rows x 4 px -> bilinear 2x2 footprint touches ~1.875 lines.
__device__ __half g_xh[Bn * DGn * Hc * Wc * CGn];
// Weights pre-permuted into per-lane HMMA B-fragment order:
// g_wb[((kk*8 + nt)*2 + ksp)*32 + lane] = 16B = {b0,b1}(ks=2ksp), {b0,b1}(ks=2ksp+1)
__device__ uint4 g_wb[KKn * 8 * 2 * 32];

#define SWZ(off) ((off) ^ (((off) >> 3) & 0x70))

// ---------------- smem: 2-deep A-buffer ring (pairwise-synced) ----------------
#define SM_ABUF(s) ((s) * 16384)
#define SM_TOTAL   32768

// pairwise named barriers (64 threads = producer warp + consumer warp):
// pair p, slot s: full = p*2+s (0..7), empty = 8+p*2+s (8..15)
#define BARP_SYNC(id)   asm volatile("bar.sync %0, 64;"   :: "r"(id) : "memory")
#define BARP_ARRIVE(id) asm volatile("bar.arrive %0, 64;" :: "r"(id) : "memory")

static __device__ __forceinline__ uint32_t smem_u32(const void* p) {
    uint32_t a;
    asm("{ .reg .u64 t; cvta.to.shared.u64 t, %1; cvt.u32.u64 %0, t; }" : "=r"(a) : "l"(p));
    return a;
}
static __device__ __forceinline__ void ldsm_x4(uint32_t* r, uint32_t addr) {
    asm volatile("ldmatrix.sync.aligned.m8n8.x4.shared.b16 {%0,%1,%2,%3}, [%4];"
                 : "=r"(r[0]), "=r"(r[1]), "=r"(r[2]), "=r"(r[3]) : "r"(addr));
}
static __device__ __forceinline__ void mma_f16(float* d, const uint32_t* a, uint32_t b0, uint32_t b1) {
    asm volatile("mma.sync.aligned.m16n8k16.row.col.f32.f16.f16.f32 "
                 "{%0,%1,%2,%3}, {%4,%5,%6,%7}, {%8,%9}, {%0,%1,%2,%3};"
                 : "+f"(d[0]), "+f"(d[1]), "+f"(d[2]), "+f"(d[3])
                 : "r"(a[0]), "r"(a[1]), "r"(a[2]), "r"(a[3]), "r"(b0), "r"(b1));
}

// ---------------------------------------------------------------------------
// Merged prep: blocks [0,1024) transpose x into the y-interleaved fp16 layout;
// blocks [1024,1033) build per-tap B fragments in per-lane order.
// ---------------------------------------------------------------------------
__global__ void prep_kernel(const float* __restrict__ x, const float* __restrict__ w) {
    const int tid = threadIdx.x;
    if (blockIdx.x < 1024) {
        __shared__ float s[8][516];
        const int blk = blockIdx.x;
        const int b   = blk >> 8;
        const int dg  = (blk >> 5) & 7;
        const int p0  = (blk & 31) * 512;            // 4 full rows (y0g..y0g+3)
        #pragma unroll
        for (int ch = 0; ch < 8; ++ch) {
            const float* src = x + (size_t)(b * CIN + dg * CGn + ch) * (Hc * Wc) + p0;
            s[ch][tid]       = src[tid];
            s[ch][tid + 256] = src[tid + 256];
        }
        __syncthreads();
        // write: tid = ybi*128 + xl; each tid emits one (y-pair, x) = 16 halves = 32B
        const int ybi = tid >> 7;                     // 0..1 (two y-pairs in block)
        const int xl  = tid & 127;
        const int yp  = (p0 >> 8) + ybi;              // global y-pair index
        __half hh[16];
        #pragma unroll
        for (int yi = 0; yi < 2; ++yi)
            #pragma unroll
            for (int ch = 0; ch < 8; ++ch)
                hh[yi * 8 + ch] = __float2half_rn(s[ch][(ybi * 2 + yi) * 128 + xl]);
        __half* dst = g_xh + (size_t)(b * DGn + dg) * (Hc * Wc * CGn)
                    + (size_t)(yp * Wc + xl) * (2 * CGn);
        *(uint4*)dst       = *(const uint4*)&hh[0];
        *(uint4*)(dst + 8) = *(const uint4*)&hh[8];
    } else {
        const int kk = blockIdx.x - 1024;
        #pragma unroll
        for (int r = 0; r < 2; ++r) {
            const int idx  = r * 256 + tid;
            const int nt   = idx >> 6;
            const int ksp  = (idx >> 5) & 1;
            const int lane = idx & 31;
            const int n    = nt * 8 + (lane >> 2);
            __half h[8];
            #pragma unroll
            for (int j = 0; j < 2; ++j) {
                const int ks = 2 * ksp + j;
                const int kb = ks * 16 + 2 * (lane & 3);
                h[j * 4 + 0] = __float2half_rn(w[(size_t)(n * CIN + kb + 0) * KKn + kk]);
                h[j * 4 + 1] = __float2half_rn(w[(size_t)(n * CIN + kb + 1) * KKn + kk]);
                h[j * 4 + 2] = __float2half_rn(w[(size_t)(n * CIN + kb + 8) * KKn + kk]);
                h[j * 4 + 3] = __float2half_rn(w[(size_t)(n * CIN + kb + 9) * KKn + kk]);
            }
            g_wb[((kk * 8 + nt) * 2 + ksp) * 32 + lane] = *(const uint4*)h;
        }
    }
}

// ---------------------------------------------------------------------------
// Warp-specialized deformable conv, pairwise-synced (R14 structure),
// gathers on the y-interleaved layout.
// ---------------------------------------------------------------------------
__global__ void __launch_bounds__(256, 2) dcn_kernel(
    const float* __restrict__ offset,
    const float* __restrict__ bias,
    float* __restrict__ out)
{
    extern __shared__ char smem[];
    const uint32_t smb = smem_u32(smem);
    const int bid = blockIdx.x;
    const int b   = bid >> 7;
    const int y   = bid & 127;
    const int tid = threadIdx.x;
    const int wid = tid >> 5;
    const int lid = tid & 31;

    if (wid >= 4) {
        // ================== PRODUCER (warps 4-7) ==================
        const int p   = wid - 4;                    // pair id; px range [p*32, p*32+32)
        const int pxl = p * 32 + lid;
        const float* off_b = offset + (size_t)b * (2 * DGn * KKn * HWp) + (size_t)y * WOn + pxl;
        const __half* xh_b = g_xh + (size_t)b * (DGn * Hc * Wc * CGn);

        // preload tap-0 offsets
        float poy[8], pox[8];
        #pragma unroll
        for (int dg = 0; dg < 8; ++dg) {
            const float* op = off_b + (size_t)(dg * KKn * 2) * HWp;
            poy[dg] = op[0];
            pox[dg] = op[HWp];
        }

        for (int kk = 0; kk < KKn; ++kk) {
            const int s = kk & 1;

            // prefetch next tap's offsets before any waiting
            float noy[8], nox[8];
            if (kk + 1 < KKn) {
                #pragma unroll
                for (int dg = 0; dg < 8; ++dg) {
                    const float* op = off_b + (size_t)((dg * KKn + kk + 1) * 2) * HWp;
                    noy[dg] = op[0];
                    nox[dg] = op[HWp];
                }
            }

            if (kk >= 2) BARP_SYNC(8 + p * 2 + s);   // consumer freed this slot
            const uint32_t abase = SM_ABUF(s);
            const int kh = kk / 3;
            const int kw = kk - kh * 3;
            const float fy = (float)(y - 1 + kh);
            const float fx = (float)(pxl - 1 + kw);

            #pragma unroll
            for (int dg = 0; dg < 8; ++dg) {
                const float py  = fy + poy[dg];
                const float pxx = fx + pox[dg];
                const float y0f = floorf(py);
                const float x0f = floorf(pxx);
                const float ly  = py - y0f;
                const float lx  = pxx - x0f;
                const int y0 = (int)y0f;
                const int x0 = (int)x0f;
                const float hy = 1.0f - ly, hx = 1.0f - lx;

                float w00 = hy * hx, w01 = hy * lx, w10 = ly * hx, w11 = ly * lx;
                const bool yv0 = (y0 >= 0) && (y0 < Hc);
                const bool yv1 = (y0 + 1 >= 0) && (y0 + 1 < Hc);
                const bool xv0 = (x0 >= 0) && (x0 < Wc);
                const bool xv1 = (x0 + 1 >= 0) && (x0 + 1 < Wc);
                if (!(yv0 && xv0)) w00 = 0.0f;
                if (!(yv0 && xv1)) w01 = 0.0f;
                if (!(yv1 && xv0)) w10 = 0.0f;
                if (!(yv1 && xv1)) w11 = 0.0f;

                const int iy0 = min(max(y0, 0), Hc - 1);
                const int iy1 = min(max(y0 + 1, 0), Hc - 1);
                const int ix0 = min(max(x0, 0), Wc - 1);
                const int ix1 = min(max(x0 + 1, 0), Wc - 1);

                // y-interleaved element index: (((y>>1)*W + x)*2 + (y&1)) * CGn
                const int r00 = ((iy0 >> 1) * Wc + ix0) * 2 + (iy0 & 1);
                const int r01 = ((iy0 >> 1) * Wc + ix1) * 2 + (iy0 & 1);
                const int r10 = ((iy1 >> 1) * Wc + ix0) * 2 + (iy1 & 1);
                const int r11 = ((iy1 >> 1) * Wc + ix1) * 2 + (iy1 & 1);

                const __half* xg = xh_b + (size_t)dg * (Hc * Wc * CGn);
                const uint4 q00 = *(const uint4*)(xg + (size_t)r00 * CGn);
                const uint4 q01 = *(const uint4*)(xg + (size_t)r01 * CGn);
                const uint4 q10 = *(const uint4*)(xg + (size_t)r10 * CGn);
                const uint4 q11 = *(const uint4*)(xg + (size_t)r11 * CGn);
                const __half2* c00 = (const __half2*)&q00;
                const __half2* c01 = (const __half2*)&q01;
                const __half2* c10 = (const __half2*)&q10;
                const __half2* c11 = (const __half2*)&q11;

                const __half2 wv00 = __float2half2_rn(w00);
                const __half2 wv01 = __float2half2_rn(w01);
                const __half2 wv10 = __float2half2_rn(w10);
                const __half2 wv11 = __float2half2_rn(w11);

                __half2 v2[4];
                #pragma unroll
                for (int j = 0; j < 4; ++j) {
                    __half2 acc = __hmul2(c00[j], wv00);
                    acc = __hfma2(c01[j], wv01, acc);
                    acc = __hfma2(c10[j], wv10, acc);
                    acc = __hfma2(c11[j], wv11, acc);
                    v2[j] = acc;
                }
                const uint32_t aoff = SWZ((uint32_t)(pxl * 128 + dg * 16));
                *(uint4*)(smem + abase + aoff) = *(const uint4*)v2;
            }
            BARP_ARRIVE(p * 2 + s);

            if (kk + 1 < KKn) {
                #pragma unroll
                for (int dg = 0; dg < 8; ++dg) {
                    poy[dg] = noy[dg];
                    pox[dg] = nox[dg];
                }
            }
        }
    } else {
        // ================== CONSUMER (warps 0-3) ==================
        const int p  = wid;                          // pair id
        const int m0 = wid * 32;                     // px tile [m0, m0+32)

        float d[2][8][4];
        #pragma unroll
        for (int i = 0; i < 2; ++i)
            #pragma unroll
            for (int j = 0; j < 8; ++j)
                #pragma unroll
                for (int k = 0; k < 4; ++k)
                    d[i][j][k] = 0.0f;

        for (int kk = 0; kk < KKn; ++kk) {
            const int s = kk & 1;
            const uint4* wbk = g_wb + (size_t)kk * (8 * 2 * 32);

            // prefetch ksp=0 B fragments BEFORE the full-barrier (ring-independent)
            uint4 bq0[8];
            #pragma unroll
            for (int ntg = 0; ntg < 8; ++ntg)
                bq0[ntg] = __ldg(&wbk[(ntg * 2 + 0) * 32 + lid]);

            BARP_SYNC(p * 2 + s);                    // my producer filled my rows
            const uint32_t abase = smb + SM_ABUF(s);
            const uint32_t akg = (uint32_t)(lid >> 4);

            // ---- ksp = 0 ----
            {
                uint32_t ah[2][2][4];
                #pragma unroll
                for (int mf = 0; mf < 2; ++mf) {
                    const uint32_t arow = (uint32_t)(m0 + mf * 16 + (lid & 15));
                    #pragma unroll
                    for (int j = 0; j < 2; ++j) {
                        const uint32_t off = SWZ(arow * 128 + (uint32_t)(j * 32) + akg * 16);
                        ldsm_x4(ah[mf][j], abase + off);
                    }
                }
                #pragma unroll
                for (int ntg = 0; ntg < 8; ++ntg) {
                    mma_f16(d[0][ntg], ah[0][0], bq0[ntg].x, bq0[ntg].y);
                    mma_f16(d[0][ntg], ah[0][1], bq0[ntg].z, bq0[ntg].w);
                    mma_f16(d[1][ntg], ah[1][0], bq0[ntg].x, bq0[ntg].y);
                    mma_f16(d[1][ntg], ah[1][1], bq0[ntg].z, bq0[ntg].w);
                }
            }
            // ---- ksp = 1 ----
            {
                uint32_t ah[2][2][4];
                #pragma unroll
                for (int mf = 0; mf < 2; ++mf) {
                    const uint32_t arow = (uint32_t)(m0 + mf * 16 + (lid & 15));
                    #pragma unroll
                    for (int j = 0; j < 2; ++j) {
                        const uint32_t off = SWZ(arow * 128 + (uint32_t)((2 + j) * 32) + akg * 16);
                        ldsm_x4(ah[mf][j], abase + off);
                    }
                }
                #pragma unroll
                for (int ntg = 0; ntg < 8; ++ntg) {
                    const uint4 bq = __ldg(&wbk[(ntg * 2 + 1) * 32 + lid]);
                    mma_f16(d[0][ntg], ah[0][0], bq.x, bq.y);
                    mma_f16(d[0][ntg], ah[0][1], bq.z, bq.w);
                    mma_f16(d[1][ntg], ah[1][0], bq.x, bq.y);
                    mma_f16(d[1][ntg], ah[1][1], bq.z, bq.w);
                }
            }
            BARP_ARRIVE(8 + p * 2 + s);              // slot free for my producer
        }

        // ---- epilogue: fragments -> global, +bias ----
        float* ob = out + (size_t)b * (COUT * HWp) + (size_t)y * WOn;
        #pragma unroll
        for (int mf = 0; mf < 2; ++mf) {
            const int px0 = m0 + mf * 16 + (lid >> 2);
            #pragma unroll
            for (int nt = 0; nt < 8; ++nt) {
                const int o0 = nt * 8 + 2 * (lid & 3);
                const float2 bv = *(const float2*)&bias[o0];
                ob[(size_t)o0 * HWp + px0]           = d[mf][nt][0] + bv.x;
                ob[(size_t)(o0 + 1) * HWp + px0]     = d[mf][nt][1] + bv.y;
                ob[(size_t)o0 * HWp + px0 + 8]       = d[mf][nt][2] + bv.x;
                ob[(size_t)(o0 + 1) * HWp + px0 + 8] = d[mf][nt][3] + bv.y;
            }
        }
    }
}

extern "C" void kernel_launch(void* const* d_in, const int* in_sizes, int n_in,
                              void* d_out, int out_size) {
    const float* x      = (const float*)d_in[0];
    const float* offset = (const float*)d_in[1];
    const float* weight = (const float*)d_in[2];
    const float* bias   = (const float*)d_in[3];
    float* out = (float*)d_out;

    cudaFuncSetAttribute(dcn_kernel, cudaFuncAttributeMaxDynamicSharedMemorySize, SM_TOTAL);

    prep_kernel<<<1024 + KKn, 256>>>(x, weight);
    dcn_kernel<<<Bn * HOn, 256, SM_TOTAL>>>(offset, bias, out);
}

// round 16
// speedup vs baseline: 1.0377x; 1.0377x over previous
#include <cuda_runtime.h>
#include <cuda_fp16.h>
#include <cstdint>

#define Bn   4
#define CIN  64
#define Hc   128
#define Wc   128
#define COUT 64
#define DGn  8
#define KKn  9
#define HOn  128
#define WOn  128
#define CGn  8
#define HWp  (HOn * WOn)

// ---------------- scratch (device globals; no runtime alloc) ----------------
__device__ __half g_xh[Bn * DGn * Hc * Wc * CGn];   // x: [b][dg][y][x][cg] fp16
// Weights pre-permuted into per-lane HMMA B-fragment order:
// g_wb[((kk*8 + nt)*2 + ksp)*32 + lane] = 16B = {b0,b1}(ks=2ksp), {b0,b1}(ks=2ksp+1)
__device__ uint4 g_wb[KKn * 8 * 2 * 32];

#define SWZ(off) ((off) ^ (((off) >> 3) & 0x70))

// ---------------- smem: 4-deep A-buffer ring ----------------
#define SM_ABUF(s) ((s) * 16384)
#define SM_TOTAL   65536

// named barriers (block-wide): full[s] = 1+s (1..4), empty[s] = 5+s (5..8)
#define BAR_SYNC(id)   asm volatile("bar.sync %0, 256;"   :: "r"(id) : "memory")
#define BAR_ARRIVE(id) asm volatile("bar.arrive %0, 256;" :: "r"(id) : "memory")

static __device__ __forceinline__ uint32_t smem_u32(const void* p) {
    uint32_t a;
    asm("{ .reg .u64 t; cvta.to.shared.u64 t, %1; cvt.u32.u64 %0, t; }" : "=r"(a) : "l"(p));
    return a;
}
static __device__ __forceinline__ void ldsm_x4(uint32_t* r, uint32_t addr) {
    asm volatile("ldmatrix.sync.aligned.m8n8.x4.shared.b16 {%0,%1,%2,%3}, [%4];"
                 : "=r"(r[0]), "=r"(r[1]), "=r"(r[2]), "=r"(r[3]) : "r"(addr));
}
static __device__ __forceinline__ void mma_f16(float* d, const uint32_t* a, uint32_t b0, uint32_t b1) {
    asm volatile("mma.sync.aligned.m16n8k16.row.col.f32.f16.f16.f32 "
                 "{%0,%1,%2,%3}, {%4,%5,%6,%7}, {%8,%9}, {%0,%1,%2,%3};"
                 : "+f"(d[0]), "+f"(d[1]), "+f"(d[2]), "+f"(d[3])
                 : "r"(a[0]), "r"(a[1]), "r"(a[2]), "r"(a[3]), "r"(b0), "r"(b1));
}

// ---------------------------------------------------------------------------
// Merged prep: blocks [0,1024) transpose x (512 px x 8ch, fp16 out);
// blocks [1024,1033) build per-tap B fragments in per-lane order.
// ---------------------------------------------------------------------------
__global__ void prep_kernel(const float* __restrict__ x, const float* __restrict__ w) {
    const int tid = threadIdx.x;
    if (blockIdx.x < 1024) {
        __shared__ float s[8][516];
        const int blk = blockIdx.x;
        const int b   = blk >> 8;
        const int dg  = (blk >> 5) & 7;
        const int p0  = (blk & 31) * 512;
        #pragma unroll
        for (int ch = 0; ch < 8; ++ch) {
            const float* src = x + (size_t)(b * CIN + dg * CGn + ch) * (Hc * Wc) + p0;
            s[ch][tid]       = src[tid];
            s[ch][tid + 256] = src[tid + 256];
        }
        __syncthreads();
        __half2* dst = (__half2*)(g_xh + ((size_t)(b * DGn + dg) * (Hc * Wc) + p0) * CGn);
        #pragma unroll
        for (int i = 0; i < 8; ++i) {
            const int j = i * 512 + tid * 2;
            dst[i * 256 + tid] = __floats2half2_rn(s[j & 7][j >> 3], s[(j + 1) & 7][(j + 1) >> 3]);
        }
    } else {
        const int kk = blockIdx.x - 1024;
        #pragma unroll
        for (int r = 0; r < 2; ++r) {
            const int idx  = r * 256 + tid;
            const int nt   = idx >> 6;
            const int ksp  = (idx >> 5) & 1;
            const int lane = idx & 31;
            const int n    = nt * 8 + (lane >> 2);
            __half h[8];
            #pragma unroll
            for (int j = 0; j < 2; ++j) {
                const int ks = 2 * ksp + j;
                const int kb = ks * 16 + 2 * (lane & 3);
                h[j * 4 + 0] = __float2half_rn(w[(size_t)(n * CIN + kb + 0) * KKn + kk]);
                h[j * 4 + 1] = __float2half_rn(w[(size_t)(n * CIN + kb + 1) * KKn + kk]);
                h[j * 4 + 2] = __float2half_rn(w[(size_t)(n * CIN + kb + 8) * KKn + kk]);
                h[j * 4 + 3] = __float2half_rn(w[(size_t)(n * CIN + kb + 9) * KKn + kk]);
            }
            g_wb[((kk * 8 + nt) * 2 + ksp) * 32 + lane] = *(const uint4*)h;
        }
    }
}

// ---------------------------------------------------------------------------
// Warp-specialized deformable conv: R13 structure (block-wide barriers,
// depth-4 ring, consumer B-prefetch) + R14's producer offset prefetch.
// Block = one output row (b,y). Producers = warps 4-7; consumers = warps 0-3.
// ---------------------------------------------------------------------------
__global__ void __launch_bounds__(256, 2) dcn_kernel(
    const float* __restrict__ offset,
    const float* __restrict__ bias,
    float* __restrict__ out)
{
    extern __shared__ char smem[];
    const uint32_t smb = smem_u32(smem);
    const int bid = blockIdx.x;
    const int b   = bid >> 7;
    const int y   = bid & 127;
    const int tid = threadIdx.x;
    const int wid = tid >> 5;
    const int lid = tid & 31;

    if (wid >= 4) {
        // ================== PRODUCER (warps 4-7) ==================
        const int pw = wid - 4;                     // 0..3: px range [pw*32, pw*32+32)
        const int pxl = pw * 32 + lid;
        const float* off_b = offset + (size_t)b * (2 * DGn * KKn * HWp) + (size_t)y * WOn + pxl;
        const __half* xh_b = g_xh + (size_t)b * (DGn * Hc * Wc * CGn);

        // preload tap-0 offsets
        float poy[8], pox[8];
        #pragma unroll
        for (int dg = 0; dg < 8; ++dg) {
            const float* op = off_b + (size_t)(dg * KKn * 2) * HWp;
            poy[dg] = op[0];
            pox[dg] = op[HWp];
        }

        for (int kk = 0; kk < KKn; ++kk) {
            const int s = kk & 3;

            // prefetch next tap's offsets before any waiting
            float noy[8], nox[8];
            if (kk + 1 < KKn) {
                #pragma unroll
                for (int dg = 0; dg < 8; ++dg) {
                    const float* op = off_b + (size_t)((dg * KKn + kk + 1) * 2) * HWp;
                    noy[dg] = op[0];
                    nox[dg] = op[HWp];
                }
            }

            if (kk >= 4) BAR_SYNC(5 + s);            // consumers freed this slot
            const uint32_t abase = SM_ABUF(s);
            const int kh = kk / 3;
            const int kw = kk - kh * 3;
            const float fy = (float)(y - 1 + kh);
            const float fx = (float)(pxl - 1 + kw);

            #pragma unroll
            for (int dg = 0; dg < 8; ++dg) {
                const float py  = fy + poy[dg];
                const float pxx = fx + pox[dg];
                const float y0f = floorf(py);
                const float x0f = floorf(pxx);
                const float ly  = py - y0f;
                const float lx  = pxx - x0f;
                const int y0 = (int)y0f;
                const int x0 = (int)x0f;
                const float hy = 1.0f - ly, hx = 1.0f - lx;

                float w00 = hy * hx, w01 = hy * lx, w10 = ly * hx, w11 = ly * lx;
                const bool yv0 = (y0 >= 0) && (y0 < Hc);
                const bool yv1 = (y0 + 1 >= 0) && (y0 + 1 < Hc);
                const bool xv0 = (x0 >= 0) && (x0 < Wc);
                const bool xv1 = (x0 + 1 >= 0) && (x0 + 1 < Wc);
                if (!(yv0 && xv0)) w00 = 0.0f;
                if (!(yv0 && xv1)) w01 = 0.0f;
                if (!(yv1 && xv0)) w10 = 0.0f;
                if (!(yv1 && xv1)) w11 = 0.0f;

                const int iy0 = min(max(y0, 0), Hc - 1);
                const int iy1 = min(max(y0 + 1, 0), Hc - 1);
                const int ix0 = min(max(x0, 0), Wc - 1);
                const int ix1 = min(max(x0 + 1, 0), Wc - 1);

                const __half* xg = xh_b + (size_t)dg * (Hc * Wc * CGn);
                const uint4 q00 = *(const uint4*)(xg + (size_t)(iy0 * Wc + ix0) * CGn);
                const uint4 q01 = *(const uint4*)(xg + (size_t)(iy0 * Wc + ix1) * CGn);
                const uint4 q10 = *(const uint4*)(xg + (size_t)(iy1 * Wc + ix0) * CGn);
                const uint4 q11 = *(const uint4*)(xg + (size_t)(iy1 * Wc + ix1) * CGn);
                const __half2* c00 = (const __half2*)&q00;
                const __half2* c01 = (const __half2*)&q01;
                const __half2* c10 = (const __half2*)&q10;
                const __half2* c11 = (const __half2*)&q11;

                const __half2 wv00 = __float2half2_rn(w00);
                const __half2 wv01 = __float2half2_rn(w01);
                const __half2 wv10 = __float2half2_rn(w10);
                const __half2 wv11 = __float2half2_rn(w11);

                __half2 v2[4];
                #pragma unroll
                for (int j = 0; j < 4; ++j) {
                    __half2 acc = __hmul2(c00[j], wv00);
                    acc = __hfma2(c01[j], wv01, acc);
                    acc = __hfma2(c10[j], wv10, acc);
                    acc = __hfma2(c11[j], wv11, acc);
                    v2[j] = acc;
                }
                const uint32_t aoff = SWZ((uint32_t)(pxl * 128 + dg * 16));
                *(uint4*)(smem + abase + aoff) = *(const uint4*)v2;
            }
            BAR_ARRIVE(1 + s);

            if (kk + 1 < KKn) {
                #pragma unroll
                for (int dg = 0; dg < 8; ++dg) {
                    poy[dg] = noy[dg];
                    pox[dg] = nox[dg];
                }
            }
        }
    } else {
        // ================== CONSUMER (warps 0-3) ==================
        const int m0 = wid * 32;                    // px tile [m0, m0+32)

        float d[2][8][4];
        #pragma unroll
        for (int i = 0; i < 2; ++i)
            #pragma unroll
            for (int j = 0; j < 8; ++j)
                #pragma unroll
                for (int k = 0; k < 4; ++k)
                    d[i][j][k] = 0.0f;

        for (int kk = 0; kk < KKn; ++kk) {
            const int s = kk & 3;
            const uint4* wbk = g_wb + (size_t)kk * (8 * 2 * 32);

            // prefetch ksp=0 B fragments BEFORE the full-barrier (ring-independent)
            uint4 bq0[8];
            #pragma unroll
            for (int ntg = 0; ntg < 8; ++ntg)
                bq0[ntg] = __ldg(&wbk[(ntg * 2 + 0) * 32 + lid]);

            BAR_SYNC(1 + s);
            const uint32_t abase = smb + SM_ABUF(s);
            const uint32_t akg = (uint32_t)(lid >> 4);

            // ---- ksp = 0 ----
            {
                uint32_t ah[2][2][4];
                #pragma unroll
                for (int mf = 0; mf < 2; ++mf) {
                    const uint32_t arow = (uint32_t)(m0 + mf * 16 + (lid & 15));
                    #pragma unroll
                    for (int j = 0; j < 2; ++j) {
                        const uint32_t off = SWZ(arow * 128 + (uint32_t)(j * 32) + akg * 16);
                        ldsm_x4(ah[mf][j], abase + off);
                    }
                }
                #pragma unroll
                for (int ntg = 0; ntg < 8; ++ntg) {
                    mma_f16(d[0][ntg], ah[0][0], bq0[ntg].x, bq0[ntg].y);
                    mma_f16(d[0][ntg], ah[0][1], bq0[ntg].z, bq0[ntg].w);
                    mma_f16(d[1][ntg], ah[1][0], bq0[ntg].x, bq0[ntg].y);
                    mma_f16(d[1][ntg], ah[1][1], bq0[ntg].z, bq0[ntg].w);
                }
            }
            // ---- ksp = 1 ----
            {
                uint32_t ah[2][2][4];
                #pragma unroll
                for (int mf = 0; mf < 2; ++mf) {
                    const uint32_t arow = (uint32_t)(m0 + mf * 16 + (lid & 15));
                    #pragma unroll
                    for (int j = 0; j < 2; ++j) {
                        const uint32_t off = SWZ(arow * 128 + (uint32_t)((2 + j) * 32) + akg * 16);
                        ldsm_x4(ah[mf][j], abase + off);
                    }
                }
                #pragma unroll
                for (int ntg = 0; ntg < 8; ++ntg) {
                    const uint4 bq = __ldg(&wbk[(ntg * 2 + 1) * 32 + lid]);
                    mma_f16(d[0][ntg], ah[0][0], bq.x, bq.y);
                    mma_f16(d[0][ntg], ah[0][1], bq.z, bq.w);
                    mma_f16(d[1][ntg], ah[1][0], bq.x, bq.y);
                    mma_f16(d[1][ntg], ah[1][1], bq.z, bq.w);
                }
            }
            BAR_ARRIVE(5 + s);
        }

        // ---- epilogue: fragments -> global, +bias ----
        float* ob = out + (size_t)b * (COUT * HWp) + (size_t)y * WOn;
        #pragma unroll
        for (int mf = 0; mf < 2; ++mf) {
            const int px0 = m0 + mf * 16 + (lid >> 2);
            #pragma unroll
            for (int nt = 0; nt < 8; ++nt) {
                const int o0 = nt * 8 + 2 * (lid & 3);
                const float2 bv = *(const float2*)&bias[o0];
                ob[(size_t)o0 * HWp + px0]           = d[mf][nt][0] + bv.x;
                ob[(size_t)(o0 + 1) * HWp + px0]     = d[mf][nt][1] + bv.y;
                ob[(size_t)o0 * HWp + px0 + 8]       = d[mf][nt][2] + bv.x;
                ob[(size_t)(o0 + 1) * HWp + px0 + 8] = d[mf][nt][3] + bv.y;
            }
        }
    }
}

extern "C" void kernel_launch(void* const* d_in, const int* in_sizes, int n_in,
                              void* d_out, int out_size) {
    const float* x      = (const float*)d_in[0];
    const float* offset = (const float*)d_in[1];
    const float* weight = (const float*)d_in[2];
    const float* bias   = (const float*)d_in[3];
    float* out = (float*)d_out;

    cudaFuncSetAttribute(dcn_kernel, cudaFuncAttributeMaxDynamicSharedMemorySize, SM_TOTAL);

    prep_kernel<<<1024 + KKn, 256>>>(x, weight);
    dcn_kernel<<<Bn * HOn, 256, SM_TOTAL>>>(offset, bias, out);
}

// round 17
// speedup vs baseline: 1.0435x; 1.0056x over previous
#include <cuda_runtime.h>
#include <cuda_fp16.h>
#include <cstdint>

#define Bn   4
#define CIN  64
#define Hc   128
#define Wc   128
#define COUT 64
#define DGn  8
#define KKn  9
#define HOn  128
#define WOn  128
#define CGn  8
#define HWp  (HOn * WOn)

// ---------------- scratch (device globals; no runtime alloc) ----------------
__device__ __half g_xh[Bn * DGn * Hc * Wc * CGn];   // x: [b][dg][y][x][cg] fp16
// Weights pre-permuted into per-lane HMMA B-fragment order:
// g_wb[((kk*8 + nt)*2 + ksp)*32 + lane] = 16B = {b0,b1}(ks=2ksp), {b0,b1}(ks=2ksp+1)
__device__ uint4 g_wb[KKn * 8 * 2 * 32];

#define SWZ(off) ((off) ^ (((off) >> 3) & 0x70))

// ---------------- smem: 4-deep A-buffer ring ----------------
#define SM_ABUF(s) ((s) * 16384)
#define SM_TOTAL   65536

// named barriers (block-wide): full[s] = 1+s (1..4), empty[s] = 5+s (5..8)
#define BAR_SYNC(id)   asm volatile("bar.sync %0, 256;"   :: "r"(id) : "memory")
#define BAR_ARRIVE(id) asm volatile("bar.arrive %0, 256;" :: "r"(id) : "memory")

static __device__ __forceinline__ uint32_t smem_u32(const void* p) {
    uint32_t a;
    asm("{ .reg .u64 t; cvta.to.shared.u64 t, %1; cvt.u32.u64 %0, t; }" : "=r"(a) : "l"(p));
    return a;
}
static __device__ __forceinline__ void ldsm_x4(uint32_t* r, uint32_t addr) {
    asm volatile("ldmatrix.sync.aligned.m8n8.x4.shared.b16 {%0,%1,%2,%3}, [%4];"
                 : "=r"(r[0]), "=r"(r[1]), "=r"(r[2]), "=r"(r[3]) : "r"(addr));
}
static __device__ __forceinline__ void mma_f16(float* d, const uint32_t* a, uint32_t b0, uint32_t b1) {
    asm volatile("mma.sync.aligned.m16n8k16.row.col.f32.f16.f16.f32 "
                 "{%0,%1,%2,%3}, {%4,%5,%6,%7}, {%8,%9}, {%0,%1,%2,%3};"
                 : "+f"(d[0]), "+f"(d[1]), "+f"(d[2]), "+f"(d[3])
                 : "r"(a[0]), "r"(a[1]), "r"(a[2]), "r"(a[3]), "r"(b0), "r"(b1));
}

// ---------------------------------------------------------------------------
// Merged prep, smem-free.
// Blocks [0,512): transpose x -> fp16 [b][dg][px][cg]. Each thread owns 4 px
// of one (b,dg): 8 coalesced channel LDGs per px (128B/warp), one uint4 store.
// Blocks [512,521): per-tap B fragments in per-lane order.
// ---------------------------------------------------------------------------
__global__ void prep_kernel(const float* __restrict__ x, const float* __restrict__ w) {
    const int tid = threadIdx.x;
    if (blockIdx.x < 512) {
        const int blk = blockIdx.x;
        const int b   = blk >> 7;                   // 128 blocks per batch
        const int dg  = (blk >> 4) & 7;             // 16 blocks per dg
        const int p0  = (blk & 15) * 1024;          // 1024 px per block
        const float* src = x + (size_t)(b * CIN + dg * CGn) * (Hc * Wc) + p0;
        __half* dstb = g_xh + ((size_t)(b * DGn + dg) * (Hc * Wc) + p0) * CGn;
        #pragma unroll
        for (int it = 0; it < 4; ++it) {
            const int px = it * 256 + tid;
            __half hh[8];
            #pragma unroll
            for (int ch = 0; ch < 8; ++ch)
                hh[ch] = __float2half_rn(src[(size_t)ch * (Hc * Wc) + px]);
            *(uint4*)(dstb + (size_t)px * CGn) = *(const uint4*)hh;
        }
    } else {
        const int kk = blockIdx.x - 512;
        #pragma unroll
        for (int r = 0; r < 2; ++r) {
            const int idx  = r * 256 + tid;
            const int nt   = idx >> 6;
            const int ksp  = (idx >> 5) & 1;
            const int lane = idx & 31;
            const int n    = nt * 8 + (lane >> 2);
            __half h[8];
            #pragma unroll
            for (int j = 0; j < 2; ++j) {
                const int ks = 2 * ksp + j;
                const int kb = ks * 16 + 2 * (lane & 3);
                h[j * 4 + 0] = __float2half_rn(w[(size_t)(n * CIN + kb + 0) * KKn + kk]);
                h[j * 4 + 1] = __float2half_rn(w[(size_t)(n * CIN + kb + 1) * KKn + kk]);
                h[j * 4 + 2] = __float2half_rn(w[(size_t)(n * CIN + kb + 8) * KKn + kk]);
                h[j * 4 + 3] = __float2half_rn(w[(size_t)(n * CIN + kb + 9) * KKn + kk]);
            }
            g_wb[((kk * 8 + nt) * 2 + ksp) * 32 + lane] = *(const uint4*)h;
        }
    }
}

// ---------------------------------------------------------------------------
// Warp-specialized deformable conv: R16 structure + early empty-release.
// Block = one output row (b,y). Producers = warps 4-7; consumers = warps 0-3.
// ---------------------------------------------------------------------------
__global__ void __launch_bounds__(256, 2) dcn_kernel(
    const float* __restrict__ offset,
    const float* __restrict__ bias,
    float* __restrict__ out)
{
    extern __shared__ char smem[];
    const uint32_t smb = smem_u32(smem);
    const int bid = blockIdx.x;
    const int b   = bid >> 7;
    const int y   = bid & 127;
    const int tid = threadIdx.x;
    const int wid = tid >> 5;
    const int lid = tid & 31;

    if (wid >= 4) {
        // ================== PRODUCER (warps 4-7) ==================
        const int pw = wid - 4;                     // 0..3: px range [pw*32, pw*32+32)
        const int pxl = pw * 32 + lid;
        const float* off_b = offset + (size_t)b * (2 * DGn * KKn * HWp) + (size_t)y * WOn + pxl;
        const __half* xh_b = g_xh + (size_t)b * (DGn * Hc * Wc * CGn);

        // preload tap-0 offsets
        float poy[8], pox[8];
        #pragma unroll
        for (int dg = 0; dg < 8; ++dg) {
            const float* op = off_b + (size_t)(dg * KKn * 2) * HWp;
            poy[dg] = op[0];
            pox[dg] = op[HWp];
        }

        for (int kk = 0; kk < KKn; ++kk) {
            const int s = kk & 3;

            // prefetch next tap's offsets before any waiting
            float noy[8], nox[8];
            if (kk + 1 < KKn) {
                #pragma unroll
                for (int dg = 0; dg < 8; ++dg) {
                    const float* op = off_b + (size_t)((dg * KKn + kk + 1) * 2) * HWp;
                    noy[dg] = op[0];
                    nox[dg] = op[HWp];
                }
            }

            if (kk >= 4) BAR_SYNC(5 + s);            // consumers freed this slot
            const uint32_t abase = SM_ABUF(s);
            const int kh = kk / 3;
            const int kw = kk - kh * 3;
            const float fy = (float)(y - 1 + kh);
            const float fx = (float)(pxl - 1 + kw);

            #pragma unroll
            for (int dg = 0; dg < 8; ++dg) {
                const float py  = fy + poy[dg];
                const float pxx = fx + pox[dg];
                const float y0f = floorf(py);
                const float x0f = floorf(pxx);
                const float ly  = py - y0f;
                const float lx  = pxx - x0f;
                const int y0 = (int)y0f;
                const int x0 = (int)x0f;
                const float hy = 1.0f - ly, hx = 1.0f - lx;

                float w00 = hy * hx, w01 = hy * lx, w10 = ly * hx, w11 = ly * lx;
                const bool yv0 = (y0 >= 0) && (y0 < Hc);
                const bool yv1 = (y0 + 1 >= 0) && (y0 + 1 < Hc);
                const bool xv0 = (x0 >= 0) && (x0 < Wc);
                const bool xv1 = (x0 + 1 >= 0) && (x0 + 1 < Wc);
                if (!(yv0 && xv0)) w00 = 0.0f;
                if (!(yv0 && xv1)) w01 = 0.0f;
                if (!(yv1 && xv0)) w10 = 0.0f;
                if (!(yv1 && xv1)) w11 = 0.0f;

                const int iy0 = min(max(y0, 0), Hc - 1);
                const int iy1 = min(max(y0 + 1, 0), Hc - 1);
                const int ix0 = min(max(x0, 0), Wc - 1);
                const int ix1 = min(max(x0 + 1, 0), Wc - 1);

                const __half* xg = xh_b + (size_t)dg * (Hc * Wc * CGn);
                const uint4 q00 = *(const uint4*)(xg + (size_t)(iy0 * Wc + ix0) * CGn);
                const uint4 q01 = *(const uint4*)(xg + (size_t)(iy0 * Wc + ix1) * CGn);
                const uint4 q10 = *(const uint4*)(xg + (size_t)(iy1 * Wc + ix0) * CGn);
                const uint4 q11 = *(const uint4*)(xg + (size_t)(iy1 * Wc + ix1) * CGn);
                const __half2* c00 = (const __half2*)&q00;
                const __half2* c01 = (const __half2*)&q01;
                const __half2* c10 = (const __half2*)&q10;
                const __half2* c11 = (const __half2*)&q11;

                const __half2 wv00 = __float2half2_rn(w00);
                const __half2 wv01 = __float2half2_rn(w01);
                const __half2 wv10 = __float2half2_rn(w10);
                const __half2 wv11 = __float2half2_rn(w11);

                __half2 v2[4];
                #pragma unroll
                for (int j = 0; j < 4; ++j) {
                    __half2 acc = __hmul2(c00[j], wv00);
                    acc = __hfma2(c01[j], wv01, acc);
                    acc = __hfma2(c10[j], wv10, acc);
                    acc = __hfma2(c11[j], wv11, acc);
                    v2[j] = acc;
                }
                const uint32_t aoff = SWZ((uint32_t)(pxl * 128 + dg * 16));
                *(uint4*)(smem + abase + aoff) = *(const uint4*)v2;
            }
            BAR_ARRIVE(1 + s);

            if (kk + 1 < KKn) {
                #pragma unroll
                for (int dg = 0; dg < 8; ++dg) {
                    poy[dg] = noy[dg];
                    pox[dg] = nox[dg];
                }
            }
        }
    } else {
        // ================== CONSUMER (warps 0-3) ==================
        const int m0 = wid * 32;                    // px tile [m0, m0+32)

        float d[2][8][4];
        #pragma unroll
        for (int i = 0; i < 2; ++i)
            #pragma unroll
            for (int j = 0; j < 8; ++j)
                #pragma unroll
                for (int k = 0; k < 4; ++k)
                    d[i][j][k] = 0.0f;

        for (int kk = 0; kk < KKn; ++kk) {
            const int s = kk & 3;
            const uint4* wbk = g_wb + (size_t)kk * (8 * 2 * 32);

            // prefetch ksp=0 B fragments BEFORE the full-barrier (ring-independent)
            uint4 bq0[8];
            #pragma unroll
            for (int ntg = 0; ntg < 8; ++ntg)
                bq0[ntg] = __ldg(&wbk[(ntg * 2 + 0) * 32 + lid]);

            BAR_SYNC(1 + s);
            const uint32_t abase = smb + SM_ABUF(s);
            const uint32_t akg = (uint32_t)(lid >> 4);

            // ---- ksp = 0: ldsm + MMA ----
            uint32_t ah1[2][2][4];                  // ksp=1 A-frags (loaded below)
            {
                uint32_t ah[2][2][4];
                #pragma unroll
                for (int mf = 0; mf < 2; ++mf) {
                    const uint32_t arow = (uint32_t)(m0 + mf * 16 + (lid & 15));
                    #pragma unroll
                    for (int j = 0; j < 2; ++j) {
                        const uint32_t off = SWZ(arow * 128 + (uint32_t)(j * 32) + akg * 16);
                        ldsm_x4(ah[mf][j], abase + off);
                    }
                }
                #pragma unroll
                for (int ntg = 0; ntg < 8; ++ntg) {
                    mma_f16(d[0][ntg], ah[0][0], bq0[ntg].x, bq0[ntg].y);
                    mma_f16(d[0][ntg], ah[0][1], bq0[ntg].z, bq0[ntg].w);
                    mma_f16(d[1][ntg], ah[1][0], bq0[ntg].x, bq0[ntg].y);
                    mma_f16(d[1][ntg], ah[1][1], bq0[ntg].z, bq0[ntg].w);
                }
            }
            // ---- ksp = 1: ldsm, release slot EARLY, then MMA ----
            {
                #pragma unroll
                for (int mf = 0; mf < 2; ++mf) {
                    const uint32_t arow = (uint32_t)(m0 + mf * 16 + (lid & 15));
                    #pragma unroll
                    for (int j = 0; j < 2; ++j) {
                        const uint32_t off = SWZ(arow * 128 + (uint32_t)((2 + j) * 32) + akg * 16);
                        ldsm_x4(ah1[mf][j], abase + off);
                    }
                }
                BAR_ARRIVE(5 + s);                  // all A reads done; slot free
                #pragma unroll
                for (int ntg = 0; ntg < 8; ++ntg) {
                    const uint4 bq = __ldg(&wbk[(ntg * 2 + 1) * 32 + lid]);
                    mma_f16(d[0][ntg], ah1[0][0], bq.x, bq.y);
                    mma_f16(d[0][ntg], ah1[0][1], bq.z, bq.w);
                    mma_f16(d[1][ntg], ah1[1][0], bq.x, bq.y);
                    mma_f16(d[1][ntg], ah1[1][1], bq.z, bq.w);
                }
            }
        }

        // ---- epilogue: fragments -> global, +bias ----
        float* ob = out + (size_t)b * (COUT * HWp) + (size_t)y * WOn;
        #pragma unroll
        for (int mf = 0; mf < 2; ++mf) {
            const int px0 = m0 + mf * 16 + (lid >> 2);
            #pragma unroll
            for (int nt = 0; nt < 8; ++nt) {
                const int o0 = nt * 8 + 2 * (lid & 3);
                const float2 bv = *(const float2*)&bias[o0];
                ob[(size_t)o0 * HWp + px0]           = d[mf][nt][0] + bv.x;
                ob[(size_t)(o0 + 1) * HWp + px0]     = d[mf][nt][1] + bv.y;
                ob[(size_t)o0 * HWp + px0 + 8]       = d[mf][nt][2] + bv.x;
                ob[(size_t)(o0 + 1) * HWp + px0 + 8] = d[mf][nt][3] + bv.y;
            }
        }
    }
}

extern "C" void kernel_launch(void* const* d_in, const int* in_sizes, int n_in,
                              void* d_out, int out_size) {
    const float* x      = (const float*)d_in[0];
    const float* offset = (const float*)d_in[1];
    const float* weight = (const float*)d_in[2];
    const float* bias   = (const float*)d_in[3];
    float* out = (float*)d_out;

    cudaFuncSetAttribute(dcn_kernel, cudaFuncAttributeMaxDynamicSharedMemorySize, SM_TOTAL);

    prep_kernel<<<512 + KKn, 256>>>(x, weight);
    dcn_kernel<<<Bn * HOn, 256, SM_TOTAL>>>(offset, bias, out);
}